// round 16
// baseline (speedup 1.0000x reference)
#include <cuda_runtime.h>
#include <cuda_fp16.h>
#include <cstdint>
#include <math.h>

#define B 2
#define DIM 384
#define HEADS 8
#define C 48
#define IMG 128
#define HW (IMG*IMG)        // 16384

// ---------------- scratch (static device globals; no allocations) ----------
__device__ __align__(16) __half g_qh[B*DIM*HW];   // dwconv(q) fp16 hi
__device__ __align__(16) __half g_ql[B*DIM*HW];   // dwconv(q) fp16 lo
__device__ __align__(16) __half g_kh[B*DIM*HW];   // dwconv(k) fp16 hi
__device__ __align__(16) __half g_kl[B*DIM*HW];   // dwconv(k) fp16 lo
__device__ __align__(16) __half g_vh[B*DIM*HW];   // dwconv(v) fp16
__device__ float g_ssq[B*DIM];
__device__ float g_ssk[B*DIM];
__device__ float g_G[B*HEADS*C*C];
__device__ float g_A[B*HEADS*C*C];
__device__ __align__(16) __half g_Mh[B*DIM*DIM];  // [b][co][k] fp16

// ================= PTX helpers (compute_103-safe: sm_80+ features) =========
__device__ __forceinline__ uint32_t smem_u32(const void* p) {
    uint32_t a;
    asm("{ .reg .u64 t; cvta.to.shared.u64 t, %1; cvt.u32.u64 %0, t; }"
        : "=r"(a) : "l"(p));
    return a;
}
__device__ __forceinline__ void cpa16(uint32_t saddr, const void* g) {
    asm volatile("cp.async.cg.shared.global [%0], [%1], 16;"
                 :: "r"(saddr), "l"(g) : "memory");
}
#define CP_COMMIT() asm volatile("cp.async.commit_group;" ::: "memory")
#define CP_WAIT1()  asm volatile("cp.async.wait_group 1;" ::: "memory")
#define CP_WAIT2()  asm volatile("cp.async.wait_group 2;" ::: "memory")

__device__ __forceinline__ void ldmA(uint32_t* a, uint32_t addr) {
    asm volatile("ldmatrix.sync.aligned.m8n8.x4.shared.b16 {%0,%1,%2,%3}, [%4];"
        : "=r"(a[0]), "=r"(a[1]), "=r"(a[2]), "=r"(a[3]) : "r"(addr));
}
__device__ __forceinline__ void ldmBt4(uint32_t* bf, uint32_t addr) {
    asm volatile("ldmatrix.sync.aligned.m8n8.x4.trans.shared.b16 {%0,%1,%2,%3}, [%4];"
        : "=r"(bf[0]), "=r"(bf[1]), "=r"(bf[2]), "=r"(bf[3]) : "r"(addr));
}
__device__ __forceinline__ void mma16816(float* c, const uint32_t* a, const uint32_t* bf) {
    asm volatile("mma.sync.aligned.m16n8k16.row.col.f32.f16.f16.f32 "
        "{%0,%1,%2,%3}, {%4,%5,%6,%7}, {%8,%9}, {%0,%1,%2,%3};"
        : "+f"(c[0]), "+f"(c[1]), "+f"(c[2]), "+f"(c[3])
        : "r"(a[0]), "r"(a[1]), "r"(a[2]), "r"(a[3]), "r"(bf[0]), "r"(bf[1]));
}

// ---------------- zero accumulators ----------------------------------------
__global__ void zero_k() {
    int i = blockIdx.x * blockDim.x + threadIdx.x;
    if (i < B*DIM) { g_ssq[i] = 0.f; g_ssk[i] = 0.f; }
    if (i < B*HEADS*C*C) g_G[i] = 0.f;
}

// ---------------- fused depthwise 3x3 convs, sliding-window rows -----------
// which = wbase + blockIdx.z: 0=q, 1=k, 2=v (v runs on a parallel stream)
__device__ __forceinline__ uint32_t pack_h2(float a, float b) {
    __half2 t(__float2half(a), __float2half(b));
    return *reinterpret_cast<uint32_t*>(&t);
}
__global__ void __launch_bounds__(256) dwconv_all(
    const float* __restrict__ qf, const float* __restrict__ kf,
    const float* __restrict__ vf, const float* __restrict__ wq,
    const float* __restrict__ wk, const float* __restrict__ wv, int wbase)
{
    int which = wbase + blockIdx.z;
    const float* in = (which == 0) ? qf : (which == 1) ? kf : vf;
    const float* w  = (which == 0) ? wq : (which == 1) ? wk : wv;
    int bc  = blockIdx.y;
    int c   = bc % DIM;
    int wid = threadIdx.x >> 5, lid = threadIdx.x & 31;
    int y0  = wid * 16;
    int x   = lid * 4;
    const float* ip = in + (size_t)bc * HW;

    float wv9[9];
#pragma unroll
    for (int i = 0; i < 9; i++) wv9[i] = w[c*9 + i];

    float4 mP, mC, mN;
    float lP, rP, lC, rC, lN, rN;

    auto loadrow = [&](int yy, float4& m, float& l, float& r) {
        if ((unsigned)yy < (unsigned)IMG) m = *(const float4*)(ip + yy*IMG + x);
        else m = make_float4(0.f, 0.f, 0.f, 0.f);
        l = __shfl_up_sync(0xffffffffu, m.w, 1);
        r = __shfl_down_sync(0xffffffffu, m.x, 1);
        if (lid == 0)  l = 0.f;
        if (lid == 31) r = 0.f;
    };

    loadrow(y0 - 1, mP, lP, rP);
    loadrow(y0,     mC, lC, rC);

    float ssum = 0.f;
#pragma unroll 4
    for (int yy = 0; yy < 16; yy++) {
        loadrow(y0 + yy + 1, mN, lN, rN);

        float a0 = wv9[0]*lP   + wv9[1]*mP.x + wv9[2]*mP.y
                 + wv9[3]*lC   + wv9[4]*mC.x + wv9[5]*mC.y
                 + wv9[6]*lN   + wv9[7]*mN.x + wv9[8]*mN.y;
        float a1 = wv9[0]*mP.x + wv9[1]*mP.y + wv9[2]*mP.z
                 + wv9[3]*mC.x + wv9[4]*mC.y + wv9[5]*mC.z
                 + wv9[6]*mN.x + wv9[7]*mN.y + wv9[8]*mN.z;
        float a2 = wv9[0]*mP.y + wv9[1]*mP.z + wv9[2]*mP.w
                 + wv9[3]*mC.y + wv9[4]*mC.z + wv9[5]*mC.w
                 + wv9[6]*mN.y + wv9[7]*mN.z + wv9[8]*mN.w;
        float a3 = wv9[0]*mP.z + wv9[1]*mP.w + wv9[2]*rP
                 + wv9[3]*mC.z + wv9[4]*mC.w + wv9[5]*rC
                 + wv9[6]*mN.z + wv9[7]*mN.w + wv9[8]*rN;

        size_t po = (size_t)bc*HW + (y0 + yy)*IMG + x;
        if (which == 2) {
            uint2 uh;
            uh.x = pack_h2(a0, a1); uh.y = pack_h2(a2, a3);
            *(uint2*)&g_vh[po] = uh;
        } else {
            float h0 = __half2float(__float2half(a0));
            float h1 = __half2float(__float2half(a1));
            float h2 = __half2float(__float2half(a2));
            float h3 = __half2float(__float2half(a3));
            uint2 uh, ul;
            uh.x = pack_h2(a0, a1); uh.y = pack_h2(a2, a3);
            ul.x = pack_h2(a0 - h0, a1 - h1); ul.y = pack_h2(a2 - h2, a3 - h3);
            __half* oh = (which == 0) ? g_qh : g_kh;
            __half* ol = (which == 0) ? g_ql : g_kl;
            *(uint2*)&oh[po] = uh;
            *(uint2*)&ol[po] = ul;
            ssum += a0*a0 + a1*a1 + a2*a2 + a3*a3;
        }
        mP = mC; lP = lC; rP = rC;
        mC = mN; lC = lN; rC = rN;
    }

    if (which < 2) {
#pragma unroll
        for (int off = 16; off > 0; off >>= 1)
            ssum += __shfl_xor_sync(0xffffffffu, ssum, off);
        __shared__ float red[8];
        if (lid == 0) red[wid] = ssum;
        __syncthreads();
        if (threadIdx.x == 0) {
            float tot = 0.f;
#pragma unroll
            for (int i = 0; i < 8; i++) tot += red[i];
            float* ssq = (which == 0) ? g_ssq : g_ssk;
            atomicAdd(&ssq[bc], tot);
        }
    }
}

// ---------------- G = Q @ K^T via tensor cores, 3-term fp16 split ----------
// 3-term split REQUIRED: top-k rank gaps ~8e-4; single-fp16 logit noise
// flips boundaries and fails 1e-3 (measured round 9).
// bh_base selects the batch half (0 -> b=0, 8 -> b=1) for pipeline overlap.
#define QK_SPLITS 32
#define QK_CHUNK (HW/QK_SPLITS)   // 512
#define QROW_B 144                // 64 fp16 = 128B + 16B pad
#define QT_BYTES (C*QROW_B)       // 6912
#define QSTG (4*QT_BYTES)         // 27648 (qh,ql,kh,kl)
#define QK_SMEM (2*QSTG)          // 55296

__global__ void __launch_bounds__(128) gemm_qk_tc(int bh_base)
{
    extern __shared__ char smem[];
    uint32_t sb = smem_u32(smem);
    int tid = threadIdx.x, w = tid >> 5, lid = tid & 31;
    int bh  = bh_base + blockIdx.y;
    size_t chbase = (size_t)bh * C * HW;

    float acc[3][6][4];
#pragma unroll
    for (int mt = 0; mt < 3; mt++)
#pragma unroll
        for (int nt = 0; nt < 6; nt++)
#pragma unroll
            for (int i = 0; i < 4; i++) acc[mt][nt][i] = 0.f;

    auto load_wave = [&](int wv, int st) {
        int px0 = blockIdx.x * QK_CHUNK + wv * 64;
#pragma unroll
        for (int t = 0; t < 4; t++) {
            const __half* src =
                ((t == 0) ? g_qh : (t == 1) ? g_ql : (t == 2) ? g_kh : g_kl) + chbase;
#pragma unroll
            for (int j = 0; j < 3; j++) {
                int i = tid + j*128;      // 0..383
                int r = i >> 3, ck = i & 7;
                cpa16(sb + st*QSTG + t*QT_BYTES + r*QROW_B + ck*16,
                      src + (size_t)r*HW + px0 + ck*8);
            }
        }
    };

    load_wave(0, 0);
    CP_COMMIT();

    for (int wv = 0; wv < 8; wv++) {
        if (wv + 1 < 8) load_wave(wv + 1, (wv + 1) & 1);
        CP_COMMIT();
        CP_WAIT1();
        __syncthreads();

        uint32_t base = sb + (wv & 1)*QSTG + w*32;   // warp's k16 slice
        uint32_t ah[3][4], al[3][4];
#pragma unroll
        for (int mt = 0; mt < 3; mt++) {
            uint32_t ao = base + (uint32_t)(mt*16 + (lid & 15))*QROW_B + ((lid >> 4) << 4);
            ldmA(ah[mt], ao);                 // q hi
            ldmA(al[mt], ao + QT_BYTES);      // q lo
        }
#pragma unroll
        for (int ntp = 0; ntp < 3; ntp++) {
            uint32_t bo = base + 2*QT_BYTES
                        + (uint32_t)(ntp*16 + ((lid >> 4) << 3) + (lid & 7))*QROW_B
                        + (((lid >> 3) & 1) << 4);
            uint32_t bh4[4], bl4[4];
            ldmA(bh4, bo);                    // k hi (non-trans x4: two n8 tiles)
            ldmA(bl4, bo + QT_BYTES);         // k lo
#pragma unroll
            for (int q = 0; q < 2; q++)
#pragma unroll
                for (int mt = 0; mt < 3; mt++) {
                    mma16816(acc[mt][ntp*2+q], ah[mt], &bh4[q*2]);
                    mma16816(acc[mt][ntp*2+q], ah[mt], &bl4[q*2]);
                    mma16816(acc[mt][ntp*2+q], al[mt], &bh4[q*2]);
                }
        }
        __syncthreads();
    }

    // ---- reduce 4 warps' tiles in smem, then one atomicAdd pass ----
    float* sred = (float*)smem;        // 48 x 49 floats, aliases stages
    int grp = lid >> 2, tg = lid & 3;
#pragma unroll
    for (int rw = 0; rw < 4; rw++) {
        if (w == rw) {
#pragma unroll
            for (int mt = 0; mt < 3; mt++)
#pragma unroll
                for (int nt = 0; nt < 6; nt++)
#pragma unroll
                    for (int i = 0; i < 4; i++) {
                        int row = mt*16 + grp + (i >> 1)*8;
                        int col = nt*8 + tg*2 + (i & 1);
                        if (rw == 0) sred[row*49 + col] = acc[mt][nt][i];
                        else         sred[row*49 + col] += acc[mt][nt][i];
                    }
        }
        __syncthreads();
    }
    float* Gb = &g_G[bh * C * C];
    for (int i = tid; i < C*C; i += 128) {
        int row = i / C, col = i % C;
        atomicAdd(&Gb[i], sred[row*49 + col]);
    }
}

// ---------------- rowcomb: warp-per-row, rank-based ------------------------
// rbase selects the batch half (0 or HEADS*C) for pipeline overlap.
__global__ void __launch_bounds__(256) rowcomb(const float* __restrict__ temp,
                                               const float* __restrict__ attw,
                                               int rbase)
{
    __shared__ float sv[8][48];
    int wid = threadIdx.x >> 5, lid = threadIdx.x & 31;
    int row = rbase + blockIdx.x * 8 + wid;
    int b   = row / (HEADS*C);
    int rem = row % (HEADS*C);
    int hd  = rem / C, c = rem % C;

    float inq = 1.f / fmaxf(sqrtf(g_ssq[b*DIM + hd*C + c]), 1e-12f);
    float t   = temp[hd];
    const float* Gr = &g_G[((b*HEADS + hd)*C + c) * C];

    float v0, v1 = -1e30f;
    {
        float ink = 1.f / fmaxf(sqrtf(g_ssk[b*DIM + hd*C + lid]), 1e-12f);
        v0 = Gr[lid] * inq * ink * t;
        sv[wid][lid] = v0;
        if (lid < 16) {
            int d = lid + 32;
            float ink2 = 1.f / fmaxf(sqrtf(g_ssk[b*DIM + hd*C + d]), 1e-12f);
            v1 = Gr[d] * inq * ink2 * t;
            sv[wid][d] = v1;
        }
    }
    __syncwarp();

    float m = fmaxf(v0, v1);
#pragma unroll
    for (int off = 16; off > 0; off >>= 1)
        m = fmaxf(m, __shfl_xor_sync(0xffffffffu, m, off));

    int r0 = 0, r1 = 0;
#pragma unroll 8
    for (int j = 0; j < C; j++) {
        float vj = sv[wid][j];
        r0 += (vj > v0) || (vj == v0 && j < lid);
        if (lid < 16) r1 += (vj > v1) || (vj == v1 && j < lid + 32);
    }
    float e0 = expf(v0 - m);
    float e1 = (lid < 16) ? expf(v1 - m) : 0.f;

    const int kl[4] = {C/2, C*2/3, C*3/4, C*4/5};
    float ds[4];
#pragma unroll
    for (int i = 0; i < 4; i++)
        ds[i] = ((r0 < kl[i]) ? e0 : 0.f) + ((lid < 16 && r1 < kl[i]) ? e1 : 0.f);
#pragma unroll
    for (int off = 16; off > 0; off >>= 1) {
#pragma unroll
        for (int i = 0; i < 4; i++)
            ds[i] += __shfl_xor_sync(0xffffffffu, ds[i], off);
    }

    float cf0 = 0.f, cf1 = 0.f;
#pragma unroll
    for (int i = 0; i < 4; i++) {
        float wdi = attw[i] / ds[i];
        if (r0 < kl[i]) cf0 += wdi;
        if (r1 < kl[i]) cf1 += wdi;
    }

    float* Ar = &g_A[((b*HEADS + hd)*C + c) * C];
    Ar[lid] = e0 * cf0;
    if (lid < 16) Ar[lid + 32] = e1 * cf1;
}

// ---------------- M[b] = Wproj @ blockdiag(A[b]) -> fp16 -------------------
// ibase selects the batch half (0 or DIM*DIM) for pipeline overlap.
__global__ void buildM(const float* __restrict__ wproj, int ibase)
{
    int idx = ibase + blockIdx.x * blockDim.x + threadIdx.x;
    int b  = idx / (DIM*DIM);
    int r  = idx % (DIM*DIM);
    int co = r / DIM;
    int g  = r % DIM;
    int hh = g / C, dl = g % C;

    const float* wp = wproj + co*DIM + hh*C;
    const float* Ac = &g_A[((b*HEADS + hh)*C) * C + dl];
    float acc = 0.f;
#pragma unroll
    for (int cc = 0; cc < C; cc++) acc += wp[cc] * Ac[cc*C];
    g_Mh[idx] = __float2half(acc);
}

// ---------------- final GEMM: M_fp16 @ V_fp16, 4-stage pipeline ------------
#define AST_B 80
#define BST_B 272
#define A_STG (128*AST_B)      // 10240
#define B_STG (32*BST_B)       // 8704
#define STG_B (A_STG + B_STG)  // 18944 per stage
#define FG_SMEM (4*STG_B)      // 75776
#define NKC 12

__global__ void __launch_bounds__(256, 2) finalgemm(float* __restrict__ y)
{
    extern __shared__ char smem[];
    uint32_t sb = smem_u32(smem);
    int tid = threadIdx.x, wid = tid >> 5, lid = tid & 31;
    int b   = blockIdx.z;
    int co0 = blockIdx.y * 128;
    int p0  = blockIdx.x * 128;
    int wm  = (wid & 1) * 64;
    int wn  = (wid >> 1) * 32;

    const __half* Mh = g_Mh + (size_t)b * DIM * DIM;
    const __half* Vh = g_vh + (size_t)b * DIM * HW;

    float acc[4][4][4];
#pragma unroll
    for (int mt = 0; mt < 4; mt++)
#pragma unroll
        for (int nt = 0; nt < 4; nt++)
#pragma unroll
            for (int i = 0; i < 4; i++) acc[mt][nt][i] = 0.f;

    auto load_chunk = [&](int kc, int st) {
        int k0 = kc * 32;
        uint32_t sbase = sb + st*STG_B;
#pragma unroll
        for (int i = tid; i < 512; i += 256) {
            int r = i >> 2, cc = i & 3;
            size_t go = (size_t)(co0 + r)*DIM + k0 + cc*8;
            cpa16(sbase + r*AST_B + cc*16, Mh + go);
        }
#pragma unroll
        for (int i = tid; i < 512; i += 256) {
            int r = i >> 4, cc = i & 15;
            size_t go = (size_t)(k0 + r)*HW + p0 + cc*8;
            cpa16(sbase + A_STG + r*BST_B + cc*16, Vh + go);
        }
    };

    load_chunk(0, 0);
    CP_COMMIT();
    load_chunk(1, 1);
    CP_COMMIT();

    for (int kc = 0; kc < NKC; kc++) {
        if (kc + 2 < NKC) load_chunk(kc + 2, (kc + 2) & 3);
        CP_COMMIT();
        CP_WAIT2();
        __syncthreads();

        uint32_t sbase = sb + (kc & 3)*STG_B;
        uint32_t aA = sbase + (wm + (lid & 15))*AST_B + ((lid >> 4) << 4);
        uint32_t aB = sbase + A_STG + (lid & 15)*BST_B + wn*2 + ((lid >> 4) << 4);

#pragma unroll
        for (int ks = 0; ks < 2; ks++) {
            uint32_t Ah[4][4];
#pragma unroll
            for (int mt = 0; mt < 4; mt++)
                ldmA(Ah[mt], aA + mt*16*AST_B + ks*32);
#pragma unroll
            for (int nt0 = 0; nt0 < 4; nt0 += 2) {
                uint32_t Bh[4];
                ldmBt4(Bh, aB + ks*16*BST_B + nt0*16);
#pragma unroll
                for (int q = 0; q < 2; q++)
#pragma unroll
                    for (int mt = 0; mt < 4; mt++)
                        mma16816(acc[mt][nt0+q], Ah[mt], &Bh[q*2]);
            }
        }
    }

    __syncthreads();
    int group = lid >> 2, tg = lid & 3;
#pragma unroll
    for (int mt = 0; mt < 4; mt++) {
        int row0 = co0 + wm + mt*16 + group;
#pragma unroll
        for (int nt = 0; nt < 4; nt++) {
            int col = p0 + wn + nt*8 + tg*2;
            size_t o0 = ((size_t)(b*DIM + row0))     * HW + col;
            size_t o1 = ((size_t)(b*DIM + row0 + 8)) * HW + col;
            *(float2*)&y[o0] = make_float2(acc[mt][nt][0], acc[mt][nt][1]);
            *(float2*)&y[o1] = make_float2(acc[mt][nt][2], acc[mt][nt][3]);
        }
    }
}

// ---------------- launch ----------------------------------------------------
extern "C" void kernel_launch(void* const* d_in, const int* in_sizes, int n_in,
                              void* d_out, int out_size)
{
    const float* k_fea = (const float*)d_in[0];
    const float* v_fea = (const float*)d_in[1];
    const float* q_fea = (const float*)d_in[2];
    const float* wq    = (const float*)d_in[3];
    const float* wk    = (const float*)d_in[4];
    const float* wv    = (const float*)d_in[5];
    const float* wproj = (const float*)d_in[6];
    const float* temp  = (const float*)d_in[7];
    const float* attw  = (const float*)d_in[8];
    float* y = (float*)d_out;

    static cudaStream_t s2 = nullptr;
    static cudaEvent_t evFork = nullptr, evQK0 = nullptr, evS2done = nullptr;
    static int init_done = 0;
    if (!init_done) {     // first (uncaptured) call only: resource creation
        cudaFuncSetAttribute(finalgemm, cudaFuncAttributeMaxDynamicSharedMemorySize,
                             FG_SMEM);
        cudaFuncSetAttribute(gemm_qk_tc, cudaFuncAttributeMaxDynamicSharedMemorySize,
                             QK_SMEM);
        cudaStreamCreateWithFlags(&s2, cudaStreamNonBlocking);
        cudaEventCreateWithFlags(&evFork, cudaEventDisableTiming);
        cudaEventCreateWithFlags(&evQK0, cudaEventDisableTiming);
        cudaEventCreateWithFlags(&evS2done, cudaEventDisableTiming);
        init_done = 1;
    }

    // fork: v-conv on s2 overlaps the whole q/k logits chain
    cudaEventRecord(evFork, 0);
    cudaStreamWaitEvent(s2, evFork, 0);
    dwconv_all<<<dim3(1, B*DIM, 1), 256, 0, s2>>>(
        q_fea, k_fea, v_fea, wq, wk, wv, 2);      // v only

    zero_k<<<(B*HEADS*C*C + 255)/256, 256>>>();

    dwconv_all<<<dim3(1, B*DIM, 2), 256>>>(
        q_fea, k_fea, v_fea, wq, wk, wv, 0);      // q and k

    // batch-split pipeline: qk(b1) overlaps rowcomb+buildM(b0)
    gemm_qk_tc<<<dim3(QK_SPLITS, HEADS), 128, QK_SMEM>>>(0);     // b = 0
    cudaEventRecord(evQK0, 0);

    gemm_qk_tc<<<dim3(QK_SPLITS, HEADS), 128, QK_SMEM>>>(HEADS); // b = 1

    // s2: after its v-conv, process b=0's logits while b=1's GEMM runs
    cudaStreamWaitEvent(s2, evQK0, 0);
    rowcomb<<<(HEADS*C)/8, 256, 0, s2>>>(temp, attw, 0);
    buildM<<<(DIM*DIM)/256, 256, 0, s2>>>(wproj, 0);
    cudaEventRecord(evS2done, s2);

    // main stream: b=1's logits
    rowcomb<<<(HEADS*C)/8, 256>>>(temp, attw, HEADS*C);
    buildM<<<(DIM*DIM)/256, 256>>>(wproj, DIM*DIM);

    cudaStreamWaitEvent(0, evS2done, 0);          // join before finalgemm
    finalgemm<<<dim3(HW/128, DIM/128, B), 256, FG_SMEM>>>(y);
}

// round 17
// speedup vs baseline: 1.0330x; 1.0330x over previous
#include <cuda_runtime.h>
#include <cuda_fp16.h>
#include <cstdint>
#include <math.h>

#define B 2
#define DIM 384
#define HEADS 8
#define C 48
#define IMG 128
#define HW (IMG*IMG)        // 16384

// ---------------- scratch (static device globals; no allocations) ----------
__device__ __align__(16) __half g_qh[B*DIM*HW];   // dwconv(q) fp16 hi
__device__ __align__(16) __half g_ql[B*DIM*HW];   // dwconv(q) fp16 lo
__device__ __align__(16) __half g_kh[B*DIM*HW];   // dwconv(k) fp16 hi
__device__ __align__(16) __half g_kl[B*DIM*HW];   // dwconv(k) fp16 lo
__device__ __align__(16) __half g_vh[B*DIM*HW];   // dwconv(v) fp16
__device__ float g_ssq[B*DIM];
__device__ float g_ssk[B*DIM];
__device__ float g_G[B*HEADS*C*C];
__device__ float g_A[B*HEADS*C*C];
__device__ __align__(16) __half g_Mh[B*DIM*DIM];  // [b][co][k] fp16

// ================= PTX helpers (compute_103-safe: sm_80+ features) =========
__device__ __forceinline__ uint32_t smem_u32(const void* p) {
    uint32_t a;
    asm("{ .reg .u64 t; cvta.to.shared.u64 t, %1; cvt.u32.u64 %0, t; }"
        : "=r"(a) : "l"(p));
    return a;
}
__device__ __forceinline__ void cpa16(uint32_t saddr, const void* g) {
    asm volatile("cp.async.cg.shared.global [%0], [%1], 16;"
                 :: "r"(saddr), "l"(g) : "memory");
}
#define CP_COMMIT() asm volatile("cp.async.commit_group;" ::: "memory")
#define CP_WAIT1()  asm volatile("cp.async.wait_group 1;" ::: "memory")
#define CP_WAIT2()  asm volatile("cp.async.wait_group 2;" ::: "memory")

__device__ __forceinline__ void ldmA(uint32_t* a, uint32_t addr) {
    asm volatile("ldmatrix.sync.aligned.m8n8.x4.shared.b16 {%0,%1,%2,%3}, [%4];"
        : "=r"(a[0]), "=r"(a[1]), "=r"(a[2]), "=r"(a[3]) : "r"(addr));
}
__device__ __forceinline__ void ldmBt4(uint32_t* bf, uint32_t addr) {
    asm volatile("ldmatrix.sync.aligned.m8n8.x4.trans.shared.b16 {%0,%1,%2,%3}, [%4];"
        : "=r"(bf[0]), "=r"(bf[1]), "=r"(bf[2]), "=r"(bf[3]) : "r"(addr));
}
__device__ __forceinline__ void mma16816(float* c, const uint32_t* a, const uint32_t* bf) {
    asm volatile("mma.sync.aligned.m16n8k16.row.col.f32.f16.f16.f32 "
        "{%0,%1,%2,%3}, {%4,%5,%6,%7}, {%8,%9}, {%0,%1,%2,%3};"
        : "+f"(c[0]), "+f"(c[1]), "+f"(c[2]), "+f"(c[3])
        : "r"(a[0]), "r"(a[1]), "r"(a[2]), "r"(a[3]), "r"(bf[0]), "r"(bf[1]));
}

// ---------------- zero accumulators ----------------------------------------
__global__ void zero_k() {
    int i = blockIdx.x * blockDim.x + threadIdx.x;
    if (i < B*DIM) { g_ssq[i] = 0.f; g_ssk[i] = 0.f; }
    if (i < B*HEADS*C*C) g_G[i] = 0.f;
}

// ---------------- fused depthwise 3x3 convs, sliding-window rows -----------
// which = wbase + blockIdx.z: 0=q, 1=k, 2=v (v runs on a parallel stream)
__device__ __forceinline__ uint32_t pack_h2(float a, float b) {
    __half2 t(__float2half(a), __float2half(b));
    return *reinterpret_cast<uint32_t*>(&t);
}
__global__ void __launch_bounds__(256) dwconv_all(
    const float* __restrict__ qf, const float* __restrict__ kf,
    const float* __restrict__ vf, const float* __restrict__ wq,
    const float* __restrict__ wk, const float* __restrict__ wv, int wbase)
{
    int which = wbase + blockIdx.z;
    const float* in = (which == 0) ? qf : (which == 1) ? kf : vf;
    const float* w  = (which == 0) ? wq : (which == 1) ? wk : wv;
    int bc  = blockIdx.y;
    int c   = bc % DIM;
    int wid = threadIdx.x >> 5, lid = threadIdx.x & 31;
    int y0  = wid * 16;
    int x   = lid * 4;
    const float* ip = in + (size_t)bc * HW;

    float wv9[9];
#pragma unroll
    for (int i = 0; i < 9; i++) wv9[i] = w[c*9 + i];

    float4 mP, mC, mN;
    float lP, rP, lC, rC, lN, rN;

    auto loadrow = [&](int yy, float4& m, float& l, float& r) {
        if ((unsigned)yy < (unsigned)IMG) m = *(const float4*)(ip + yy*IMG + x);
        else m = make_float4(0.f, 0.f, 0.f, 0.f);
        l = __shfl_up_sync(0xffffffffu, m.w, 1);
        r = __shfl_down_sync(0xffffffffu, m.x, 1);
        if (lid == 0)  l = 0.f;
        if (lid == 31) r = 0.f;
    };

    loadrow(y0 - 1, mP, lP, rP);
    loadrow(y0,     mC, lC, rC);

    float ssum = 0.f;
#pragma unroll 4
    for (int yy = 0; yy < 16; yy++) {
        loadrow(y0 + yy + 1, mN, lN, rN);

        float a0 = wv9[0]*lP   + wv9[1]*mP.x + wv9[2]*mP.y
                 + wv9[3]*lC   + wv9[4]*mC.x + wv9[5]*mC.y
                 + wv9[6]*lN   + wv9[7]*mN.x + wv9[8]*mN.y;
        float a1 = wv9[0]*mP.x + wv9[1]*mP.y + wv9[2]*mP.z
                 + wv9[3]*mC.x + wv9[4]*mC.y + wv9[5]*mC.z
                 + wv9[6]*mN.x + wv9[7]*mN.y + wv9[8]*mN.z;
        float a2 = wv9[0]*mP.y + wv9[1]*mP.z + wv9[2]*mP.w
                 + wv9[3]*mC.y + wv9[4]*mC.z + wv9[5]*mC.w
                 + wv9[6]*mN.y + wv9[7]*mN.z + wv9[8]*mN.w;
        float a3 = wv9[0]*mP.z + wv9[1]*mP.w + wv9[2]*rP
                 + wv9[3]*mC.z + wv9[4]*mC.w + wv9[5]*rC
                 + wv9[6]*mN.z + wv9[7]*mN.w + wv9[8]*rN;

        size_t po = (size_t)bc*HW + (y0 + yy)*IMG + x;
        if (which == 2) {
            uint2 uh;
            uh.x = pack_h2(a0, a1); uh.y = pack_h2(a2, a3);
            *(uint2*)&g_vh[po] = uh;
        } else {
            float h0 = __half2float(__float2half(a0));
            float h1 = __half2float(__float2half(a1));
            float h2 = __half2float(__float2half(a2));
            float h3 = __half2float(__float2half(a3));
            uint2 uh, ul;
            uh.x = pack_h2(a0, a1); uh.y = pack_h2(a2, a3);
            ul.x = pack_h2(a0 - h0, a1 - h1); ul.y = pack_h2(a2 - h2, a3 - h3);
            __half* oh = (which == 0) ? g_qh : g_kh;
            __half* ol = (which == 0) ? g_ql : g_kl;
            *(uint2*)&oh[po] = uh;
            *(uint2*)&ol[po] = ul;
            ssum += a0*a0 + a1*a1 + a2*a2 + a3*a3;
        }
        mP = mC; lP = lC; rP = rC;
        mC = mN; lC = lN; rC = rN;
    }

    if (which < 2) {
#pragma unroll
        for (int off = 16; off > 0; off >>= 1)
            ssum += __shfl_xor_sync(0xffffffffu, ssum, off);
        __shared__ float red[8];
        if (lid == 0) red[wid] = ssum;
        __syncthreads();
        if (threadIdx.x == 0) {
            float tot = 0.f;
#pragma unroll
            for (int i = 0; i < 8; i++) tot += red[i];
            float* ssq = (which == 0) ? g_ssq : g_ssk;
            atomicAdd(&ssq[bc], tot);
        }
    }
}

// ---------------- G = Q @ K^T via tensor cores, 3-term fp16 split ----------
// 3-term split REQUIRED: top-k rank gaps ~8e-4; single-fp16 logit noise
// flips boundaries and fails 1e-3 (measured round 9).
// bh_base selects the batch half; the two halves run CONCURRENTLY on two
// streams so combined residency equals the single-launch case.
#define QK_SPLITS 32
#define QK_CHUNK (HW/QK_SPLITS)   // 512
#define QROW_B 144                // 64 fp16 = 128B + 16B pad
#define QT_BYTES (C*QROW_B)       // 6912
#define QSTG (4*QT_BYTES)         // 27648 (qh,ql,kh,kl)
#define QK_SMEM (2*QSTG)          // 55296

__global__ void __launch_bounds__(128) gemm_qk_tc(int bh_base)
{
    extern __shared__ char smem[];
    uint32_t sb = smem_u32(smem);
    int tid = threadIdx.x, w = tid >> 5, lid = tid & 31;
    int bh  = bh_base + blockIdx.y;
    size_t chbase = (size_t)bh * C * HW;

    float acc[3][6][4];
#pragma unroll
    for (int mt = 0; mt < 3; mt++)
#pragma unroll
        for (int nt = 0; nt < 6; nt++)
#pragma unroll
            for (int i = 0; i < 4; i++) acc[mt][nt][i] = 0.f;

    auto load_wave = [&](int wv, int st) {
        int px0 = blockIdx.x * QK_CHUNK + wv * 64;
#pragma unroll
        for (int t = 0; t < 4; t++) {
            const __half* src =
                ((t == 0) ? g_qh : (t == 1) ? g_ql : (t == 2) ? g_kh : g_kl) + chbase;
#pragma unroll
            for (int j = 0; j < 3; j++) {
                int i = tid + j*128;      // 0..383
                int r = i >> 3, ck = i & 7;
                cpa16(sb + st*QSTG + t*QT_BYTES + r*QROW_B + ck*16,
                      src + (size_t)r*HW + px0 + ck*8);
            }
        }
    };

    load_wave(0, 0);
    CP_COMMIT();

    for (int wv = 0; wv < 8; wv++) {
        if (wv + 1 < 8) load_wave(wv + 1, (wv + 1) & 1);
        CP_COMMIT();
        CP_WAIT1();
        __syncthreads();

        uint32_t base = sb + (wv & 1)*QSTG + w*32;   // warp's k16 slice
        uint32_t ah[3][4], al[3][4];
#pragma unroll
        for (int mt = 0; mt < 3; mt++) {
            uint32_t ao = base + (uint32_t)(mt*16 + (lid & 15))*QROW_B + ((lid >> 4) << 4);
            ldmA(ah[mt], ao);                 // q hi
            ldmA(al[mt], ao + QT_BYTES);      // q lo
        }
#pragma unroll
        for (int ntp = 0; ntp < 3; ntp++) {
            uint32_t bo = base + 2*QT_BYTES
                        + (uint32_t)(ntp*16 + ((lid >> 4) << 3) + (lid & 7))*QROW_B
                        + (((lid >> 3) & 1) << 4);
            uint32_t bh4[4], bl4[4];
            ldmA(bh4, bo);                    // k hi (non-trans x4: two n8 tiles)
            ldmA(bl4, bo + QT_BYTES);         // k lo
#pragma unroll
            for (int q = 0; q < 2; q++)
#pragma unroll
                for (int mt = 0; mt < 3; mt++) {
                    mma16816(acc[mt][ntp*2+q], ah[mt], &bh4[q*2]);
                    mma16816(acc[mt][ntp*2+q], ah[mt], &bl4[q*2]);
                    mma16816(acc[mt][ntp*2+q], al[mt], &bh4[q*2]);
                }
        }
        __syncthreads();
    }

    // ---- reduce 4 warps' tiles in smem, then one atomicAdd pass ----
    float* sred = (float*)smem;        // 48 x 49 floats, aliases stages
    int grp = lid >> 2, tg = lid & 3;
#pragma unroll
    for (int rw = 0; rw < 4; rw++) {
        if (w == rw) {
#pragma unroll
            for (int mt = 0; mt < 3; mt++)
#pragma unroll
                for (int nt = 0; nt < 6; nt++)
#pragma unroll
                    for (int i = 0; i < 4; i++) {
                        int row = mt*16 + grp + (i >> 1)*8;
                        int col = nt*8 + tg*2 + (i & 1);
                        if (rw == 0) sred[row*49 + col] = acc[mt][nt][i];
                        else         sred[row*49 + col] += acc[mt][nt][i];
                    }
        }
        __syncthreads();
    }
    float* Gb = &g_G[bh * C * C];
    for (int i = tid; i < C*C; i += 128) {
        int row = i / C, col = i % C;
        atomicAdd(&Gb[i], sred[row*49 + col]);
    }
}

// ---------------- rowcomb: warp-per-row, rank-based ------------------------
__global__ void __launch_bounds__(256) rowcomb(const float* __restrict__ temp,
                                               const float* __restrict__ attw,
                                               int rbase)
{
    __shared__ float sv[8][48];
    int wid = threadIdx.x >> 5, lid = threadIdx.x & 31;
    int row = rbase + blockIdx.x * 8 + wid;
    int b   = row / (HEADS*C);
    int rem = row % (HEADS*C);
    int hd  = rem / C, c = rem % C;

    float inq = 1.f / fmaxf(sqrtf(g_ssq[b*DIM + hd*C + c]), 1e-12f);
    float t   = temp[hd];
    const float* Gr = &g_G[((b*HEADS + hd)*C + c) * C];

    float v0, v1 = -1e30f;
    {
        float ink = 1.f / fmaxf(sqrtf(g_ssk[b*DIM + hd*C + lid]), 1e-12f);
        v0 = Gr[lid] * inq * ink * t;
        sv[wid][lid] = v0;
        if (lid < 16) {
            int d = lid + 32;
            float ink2 = 1.f / fmaxf(sqrtf(g_ssk[b*DIM + hd*C + d]), 1e-12f);
            v1 = Gr[d] * inq * ink2 * t;
            sv[wid][d] = v1;
        }
    }
    __syncwarp();

    float m = fmaxf(v0, v1);
#pragma unroll
    for (int off = 16; off > 0; off >>= 1)
        m = fmaxf(m, __shfl_xor_sync(0xffffffffu, m, off));

    int r0 = 0, r1 = 0;
#pragma unroll 8
    for (int j = 0; j < C; j++) {
        float vj = sv[wid][j];
        r0 += (vj > v0) || (vj == v0 && j < lid);
        if (lid < 16) r1 += (vj > v1) || (vj == v1 && j < lid + 32);
    }
    float e0 = expf(v0 - m);
    float e1 = (lid < 16) ? expf(v1 - m) : 0.f;

    const int kl[4] = {C/2, C*2/3, C*3/4, C*4/5};
    float ds[4];
#pragma unroll
    for (int i = 0; i < 4; i++)
        ds[i] = ((r0 < kl[i]) ? e0 : 0.f) + ((lid < 16 && r1 < kl[i]) ? e1 : 0.f);
#pragma unroll
    for (int off = 16; off > 0; off >>= 1) {
#pragma unroll
        for (int i = 0; i < 4; i++)
            ds[i] += __shfl_xor_sync(0xffffffffu, ds[i], off);
    }

    float cf0 = 0.f, cf1 = 0.f;
#pragma unroll
    for (int i = 0; i < 4; i++) {
        float wdi = attw[i] / ds[i];
        if (r0 < kl[i]) cf0 += wdi;
        if (r1 < kl[i]) cf1 += wdi;
    }

    float* Ar = &g_A[((b*HEADS + hd)*C + c) * C];
    Ar[lid] = e0 * cf0;
    if (lid < 16) Ar[lid + 32] = e1 * cf1;
}

// ---------------- M[b] = Wproj @ blockdiag(A[b]) -> fp16 -------------------
__global__ void buildM(const float* __restrict__ wproj, int ibase)
{
    int idx = ibase + blockIdx.x * blockDim.x + threadIdx.x;
    int b  = idx / (DIM*DIM);
    int r  = idx % (DIM*DIM);
    int co = r / DIM;
    int g  = r % DIM;
    int hh = g / C, dl = g % C;

    const float* wp = wproj + co*DIM + hh*C;
    const float* Ac = &g_A[((b*HEADS + hh)*C) * C + dl];
    float acc = 0.f;
#pragma unroll
    for (int cc = 0; cc < C; cc++) acc += wp[cc] * Ac[cc*C];
    g_Mh[idx] = __float2half(acc);
}

// ---------------- final GEMM: M_fp16 @ V_fp16, 4-stage pipeline ------------
#define AST_B 80
#define BST_B 272
#define A_STG (128*AST_B)      // 10240
#define B_STG (32*BST_B)       // 8704
#define STG_B (A_STG + B_STG)  // 18944 per stage
#define FG_SMEM (4*STG_B)      // 75776
#define NKC 12

__global__ void __launch_bounds__(256, 2) finalgemm(float* __restrict__ y)
{
    extern __shared__ char smem[];
    uint32_t sb = smem_u32(smem);
    int tid = threadIdx.x, wid = tid >> 5, lid = tid & 31;
    int b   = blockIdx.z;
    int co0 = blockIdx.y * 128;
    int p0  = blockIdx.x * 128;
    int wm  = (wid & 1) * 64;
    int wn  = (wid >> 1) * 32;

    const __half* Mh = g_Mh + (size_t)b * DIM * DIM;
    const __half* Vh = g_vh + (size_t)b * DIM * HW;

    float acc[4][4][4];
#pragma unroll
    for (int mt = 0; mt < 4; mt++)
#pragma unroll
        for (int nt = 0; nt < 4; nt++)
#pragma unroll
            for (int i = 0; i < 4; i++) acc[mt][nt][i] = 0.f;

    auto load_chunk = [&](int kc, int st) {
        int k0 = kc * 32;
        uint32_t sbase = sb + st*STG_B;
#pragma unroll
        for (int i = tid; i < 512; i += 256) {
            int r = i >> 2, cc = i & 3;
            size_t go = (size_t)(co0 + r)*DIM + k0 + cc*8;
            cpa16(sbase + r*AST_B + cc*16, Mh + go);
        }
#pragma unroll
        for (int i = tid; i < 512; i += 256) {
            int r = i >> 4, cc = i & 15;
            size_t go = (size_t)(k0 + r)*HW + p0 + cc*8;
            cpa16(sbase + A_STG + r*BST_B + cc*16, Vh + go);
        }
    };

    load_chunk(0, 0);
    CP_COMMIT();
    load_chunk(1, 1);
    CP_COMMIT();

    for (int kc = 0; kc < NKC; kc++) {
        if (kc + 2 < NKC) load_chunk(kc + 2, (kc + 2) & 3);
        CP_COMMIT();
        CP_WAIT2();
        __syncthreads();

        uint32_t sbase = sb + (kc & 3)*STG_B;
        uint32_t aA = sbase + (wm + (lid & 15))*AST_B + ((lid >> 4) << 4);
        uint32_t aB = sbase + A_STG + (lid & 15)*BST_B + wn*2 + ((lid >> 4) << 4);

#pragma unroll
        for (int ks = 0; ks < 2; ks++) {
            uint32_t Ah[4][4];
#pragma unroll
            for (int mt = 0; mt < 4; mt++)
                ldmA(Ah[mt], aA + mt*16*AST_B + ks*32);
#pragma unroll
            for (int nt0 = 0; nt0 < 4; nt0 += 2) {
                uint32_t Bh[4];
                ldmBt4(Bh, aB + ks*16*BST_B + nt0*16);
#pragma unroll
                for (int q = 0; q < 2; q++)
#pragma unroll
                    for (int mt = 0; mt < 4; mt++)
                        mma16816(acc[mt][nt0+q], Ah[mt], &Bh[q*2]);
            }
        }
    }

    __syncthreads();
    int group = lid >> 2, tg = lid & 3;
#pragma unroll
    for (int mt = 0; mt < 4; mt++) {
        int row0 = co0 + wm + mt*16 + group;
#pragma unroll
        for (int nt = 0; nt < 4; nt++) {
            int col = p0 + wn + nt*8 + tg*2;
            size_t o0 = ((size_t)(b*DIM + row0))     * HW + col;
            size_t o1 = ((size_t)(b*DIM + row0 + 8)) * HW + col;
            *(float2*)&y[o0] = make_float2(acc[mt][nt][0], acc[mt][nt][1]);
            *(float2*)&y[o1] = make_float2(acc[mt][nt][2], acc[mt][nt][3]);
        }
    }
}

// ---------------- launch ----------------------------------------------------
extern "C" void kernel_launch(void* const* d_in, const int* in_sizes, int n_in,
                              void* d_out, int out_size)
{
    const float* k_fea = (const float*)d_in[0];
    const float* v_fea = (const float*)d_in[1];
    const float* q_fea = (const float*)d_in[2];
    const float* wq    = (const float*)d_in[3];
    const float* wk    = (const float*)d_in[4];
    const float* wv    = (const float*)d_in[5];
    const float* wproj = (const float*)d_in[6];
    const float* temp  = (const float*)d_in[7];
    const float* attw  = (const float*)d_in[8];
    float* y = (float*)d_out;

    static cudaStream_t s2 = nullptr;
    static cudaEvent_t evFork = nullptr, evConvQK = nullptr, evS2done = nullptr;
    static int init_done = 0;
    if (!init_done) {     // first (uncaptured) call only: resource creation
        cudaFuncSetAttribute(finalgemm, cudaFuncAttributeMaxDynamicSharedMemorySize,
                             FG_SMEM);
        cudaFuncSetAttribute(gemm_qk_tc, cudaFuncAttributeMaxDynamicSharedMemorySize,
                             QK_SMEM);
        cudaStreamCreateWithFlags(&s2, cudaStreamNonBlocking);
        cudaEventCreateWithFlags(&evFork, cudaEventDisableTiming);
        cudaEventCreateWithFlags(&evConvQK, cudaEventDisableTiming);
        cudaEventCreateWithFlags(&evS2done, cudaEventDisableTiming);
        init_done = 1;
    }

    // fork: v-conv on s2 overlaps zero + q/k conv on s0
    cudaEventRecord(evFork, 0);
    cudaStreamWaitEvent(s2, evFork, 0);
    dwconv_all<<<dim3(1, B*DIM, 1), 256, 0, s2>>>(
        q_fea, k_fea, v_fea, wq, wk, wv, 2);      // v only

    zero_k<<<(B*HEADS*C*C + 255)/256, 256>>>();
    dwconv_all<<<dim3(1, B*DIM, 2), 256>>>(
        q_fea, k_fea, v_fea, wq, wk, wv, 0);      // q and k
    cudaEventRecord(evConvQK, 0);

    // both qk halves run CONCURRENTLY (combined residency = full machine),
    // then each stream processes its batch's logits independently
    gemm_qk_tc<<<dim3(QK_SPLITS, HEADS), 128, QK_SMEM>>>(0);           // b=0, s0
    rowcomb<<<(HEADS*C)/8, 256>>>(temp, attw, 0);
    buildM<<<(DIM*DIM)/256, 256>>>(wproj, 0);

    cudaStreamWaitEvent(s2, evConvQK, 0);
    gemm_qk_tc<<<dim3(QK_SPLITS, HEADS), 128, QK_SMEM, s2>>>(HEADS);   // b=1, s2
    rowcomb<<<(HEADS*C)/8, 256, 0, s2>>>(temp, attw, HEADS*C);
    buildM<<<(DIM*DIM)/256, 256, 0, s2>>>(wproj, DIM*DIM);
    cudaEventRecord(evS2done, s2);

    cudaStreamWaitEvent(0, evS2done, 0);          // join before finalgemm
    finalgemm<<<dim3(HW/128, DIM/128, B), 256, FG_SMEM>>>(y);
}